// round 8
// baseline (speedup 1.0000x reference)
#include <cuda_runtime.h>
#include <cuda_bf16.h>
#include <cstdint>

// ---------------- problem constants ----------------
#define Bb 8
#define Cc 512
#define Tt 4096
#define Gg 2
#define NCc 1024
#define Ee 256
#define Nrows (Bb * Tt)          // 32768 rows per group
#define QELEMS (Bb * Cc * Tt)    // 16777216
#define BM 128                   // rows per CTA
#define BNC 64                   // codes per chunk
#define NCHUNK (NCc / BNC)       // 16
#define NTHREADS 256
#define ROWTILES (Nrows / BM)    // 256
#define KCAND 8                  // per (row, col-half) -> 16 per row

#define SAP 264                  // bf16 elems per staged row (528B, conflict-free ldmatrix)
#define SDP 66                   // float stride of D scratch tile (128*66*4 = 33792)

// ---------------- smem layout (bytes) ----------------
#define SM_A    0                             // 128*SAP bf16 = 67584
#define SM_B    (BM * SAP * 2)                // 67584: B stage / D overlay (33792)
#define SM_CN   (SM_B + BNC * SAP * 2)        // 101376: 64 f32 cnorm chunk
#define SM_CAND (SM_CN + 256)                 // 101632: 128*16 ints = 8192
#define SM_XN   (SM_CAND + 8192)              // 109824: 64 f32
#define SM_WIN  (SM_XN + 256)                 // 110080: 64 ints
#define SM_RED  (SM_WIN + 256 + 512)          // 110848: 256 f64 (8B aligned)
#define SM_TOTAL (SM_RED + 2048)              // 112896
#define XS_STRIDE 257                         // fp32 64-row overlay at SM_A (65792 B)

// ---------------- scratch ----------------
__device__ float  g_resid[QELEMS];
__device__ float  g_cnorm[2 * Gg * NCc];
__device__ double g_partial[2 * Gg * ROWTILES];   // 1024

// ---------------- helpers ----------------
__device__ __forceinline__ uint32_t smem_u32(const void* p) {
    uint32_t a;
    asm("{ .reg .u64 t; cvta.to.shared.u64 t, %1; cvt.u32.u64 %0, t; }"
        : "=r"(a) : "l"(p));
    return a;
}

__device__ __forceinline__ void ldsm_x4(uint32_t* r, uint32_t addr) {
    asm volatile("ldmatrix.sync.aligned.m8n8.x4.shared.b16 {%0,%1,%2,%3}, [%4];"
                 : "=r"(r[0]), "=r"(r[1]), "=r"(r[2]), "=r"(r[3]) : "r"(addr));
}

__device__ __forceinline__ void mma16816(float* c, const uint32_t* a,
                                         uint32_t b0, uint32_t b1) {
    asm volatile(
        "mma.sync.aligned.m16n8k16.row.col.f32.bf16.bf16.f32 "
        "{%0,%1,%2,%3}, {%4,%5,%6,%7}, {%8,%9}, {%0,%1,%2,%3};"
        : "+f"(c[0]), "+f"(c[1]), "+f"(c[2]), "+f"(c[3])
        : "r"(a[0]), "r"(a[1]), "r"(a[2]), "r"(a[3]), "r"(b0), "r"(b1));
}

// ---------------------------------------------------------------------------
__global__ void cnorm_kernel(const float* __restrict__ cb1,
                             const float* __restrict__ cb2) {
    int gwarp = (blockIdx.x * blockDim.x + threadIdx.x) >> 5;
    int lane  = threadIdx.x & 31;
    if (gwarp >= 2 * Gg * NCc) return;
    const float* cb = (gwarp < Gg * NCc) ? cb1 : cb2;
    int row = gwarp & (Gg * NCc - 1);
    const float* p = cb + (size_t)row * Ee;
    float s = 0.f;
#pragma unroll
    for (int i = 0; i < Ee / 32; i++) {
        float v = p[lane + i * 32];
        s = __fadd_rn(s, __fmul_rn(v, v));
    }
#pragma unroll
    for (int off = 16; off; off >>= 1) s += __shfl_xor_sync(0xffffffffu, s, off);
    if (lane == 0) g_cnorm[gwarp] = s;
}

// ---------------------------------------------------------------------------
__global__ __launch_bounds__(NTHREADS, 2)
void vq_step_mma(const float* __restrict__ xin,
                 const float* __restrict__ cb,
                 float* __restrict__ qout,
                 float* __restrict__ idxout,
                 int step) {
    extern __shared__ char sm[];
    uint32_t smb = smem_u32(sm);
    float* cnormS = (float*)(sm + SM_CN);
    int*   cands  = (int*)(sm + SM_CAND);
    float* sxn    = (float*)(sm + SM_XN);
    int*   win    = (int*)(sm + SM_WIN);
    double* sred  = (double*)(sm + SM_RED);
    float* xs     = (float*)(sm + SM_A);          // 64-row rescore overlay

    const float* src = step ? g_resid : xin;
    const float* cnorm = g_cnorm + step * (Gg * NCc);
    double* partial = g_partial + step * (Gg * ROWTILES);

    int tid  = threadIdx.x;
    int lane = tid & 31;
    int wid  = tid >> 5;
    int wm   = wid & 3;         // m quarter (32 rows)
    int wn   = wid >> 2;        // n half (32 codes)
    int g    = blockIdx.y;
    int n0   = blockIdx.x * BM;
    int b    = n0 >> 12;
    int t0   = n0 & (Tt - 1);
    size_t xbase = ((size_t)b * Cc + (size_t)g * Ee) * Tt + t0;
    const float* cbg = cb + (size_t)g * NCc * Ee;

    // ---- stage A: x[128 t-rows x 256 e] fp32 -> bf16, row stride SAP ----
#pragma unroll
    for (int i = 0; i < 16; i++) {                 // 4096 (e-pair, t4) tasks
        int f  = tid + i * NTHREADS;
        int e  = (f >> 5) << 1;                    // even e (0..254)
        int t4 = (f & 31) << 2;                    // 0..124
        float4 v0 = *(const float4*)(src + xbase + (size_t)e * Tt + t4);
        float4 v1 = *(const float4*)(src + xbase + (size_t)(e + 1) * Tt + t4);
        __nv_bfloat162 h0 = __floats2bfloat162_rn(v0.x, v1.x);
        __nv_bfloat162 h1 = __floats2bfloat162_rn(v0.y, v1.y);
        __nv_bfloat162 h2 = __floats2bfloat162_rn(v0.z, v1.z);
        __nv_bfloat162 h3 = __floats2bfloat162_rn(v0.w, v1.w);
        *(uint32_t*)(sm + SM_A + (size_t)((t4 + 0) * SAP + e) * 2) = *(uint32_t*)&h0;
        *(uint32_t*)(sm + SM_A + (size_t)((t4 + 1) * SAP + e) * 2) = *(uint32_t*)&h1;
        *(uint32_t*)(sm + SM_A + (size_t)((t4 + 2) * SAP + e) * 2) = *(uint32_t*)&h2;
        *(uint32_t*)(sm + SM_A + (size_t)((t4 + 3) * SAP + e) * 2) = *(uint32_t*)&h3;
    }

    // ldmatrix base addresses (bytes)
    uint32_t aAddr = smb + SM_A +
        (uint32_t)(((wm * 32 + (lane & 15)) * SAP + ((lane >> 4) << 3)) * 2);
    uint32_t bAddr = smb + SM_B +
        (uint32_t)(((wn * 32 + (lane & 7) + ((lane >> 4) << 3)) * SAP +
                    (((lane >> 3) & 1) << 3)) * 2);

    // per-thread top-K: row = tid&127, col-half = tid>>7 (32 cols each)
    float cd[KCAND];
    int   ci[KCAND];
#pragma unroll
    for (int s = 0; s < KCAND; s++) { cd[s] = __int_as_float(0x7f800000); ci[s] = 0; }
    float worst = __int_as_float(0x7f800000);
    int scanrow  = tid & 127;
    int scanhalf = tid >> 7;

    for (int ct = 0; ct < NCHUNK; ct++) {
        int c0 = ct * BNC;
        // ---- stage B chunk: codes [c0, c0+64) x 256 e -> bf16 stride SAP ----
#pragma unroll
        for (int i = 0; i < 16; i++) {             // 4096 (code,k4) tasks
            int f4 = tid + i * NTHREADS;
            int code = f4 >> 6;                    // 0..63
            int k4 = (f4 & 63) << 2;
            float4 v = *(const float4*)(cbg + (size_t)(c0 + code) * Ee + k4);
            __nv_bfloat162 h0 = __floats2bfloat162_rn(v.x, v.y);
            __nv_bfloat162 h1 = __floats2bfloat162_rn(v.z, v.w);
            *(uint2*)(sm + SM_B + (size_t)(code * SAP + k4) * 2) =
                make_uint2(*(uint32_t*)&h0, *(uint32_t*)&h1);
        }
        if (tid < BNC) cnormS[tid] = cnorm[g * NCc + c0 + tid];
        __syncthreads();

        // ---- GEMM: warp 32x32 tile, K=256 via 16 k-steps ----
        float acc[2][4][4];
#pragma unroll
        for (int i = 0; i < 2; i++)
#pragma unroll
            for (int j = 0; j < 4; j++)
#pragma unroll
                for (int r = 0; r < 4; r++) acc[i][j][r] = 0.f;

#pragma unroll 4
        for (int ks = 0; ks < 16; ks++) {
            uint32_t afr[2][4];
#pragma unroll
            for (int i = 0; i < 2; i++)
                ldsm_x4(afr[i], aAddr + (uint32_t)((i * 16 * SAP + ks * 16) * 2));
            uint32_t bfr[2][4];
#pragma unroll
            for (int jp = 0; jp < 2; jp++)
                ldsm_x4(bfr[jp], bAddr + (uint32_t)((jp * 16 * SAP + ks * 16) * 2));
#pragma unroll
            for (int i = 0; i < 2; i++)
#pragma unroll
                for (int j = 0; j < 4; j++)
                    mma16816(acc[i][j], afr[i],
                             bfr[j >> 1][(j & 1) * 2], bfr[j >> 1][(j & 1) * 2 + 1]);
        }
        __syncthreads();   // all warps done reading sB before D overlay

        // ---- dump D tile (dot products) into sB region, stride SDP ----
#pragma unroll
        for (int i = 0; i < 2; i++)
#pragma unroll
            for (int j = 0; j < 4; j++) {
                int m = wm * 32 + i * 16 + (lane >> 2);
                int n = wn * 32 + j * 8 + ((lane & 3) << 1);
                *(float2*)(sm + SM_B + (size_t)(m * SDP + n) * 4) =
                    make_float2(acc[i][j][0], acc[i][j][1]);
                *(float2*)(sm + SM_B + (size_t)((m + 8) * SDP + n) * 4) =
                    make_float2(acc[i][j][2], acc[i][j][3]);
            }
        __syncthreads();

        // ---- scan: all 256 threads; thread = (row, 32-col half) ----
        {
            const float* sD = (const float*)(sm + SM_B) + scanrow * SDP + scanhalf * 32;
            const float* cn = cnormS + scanhalf * 32;
            int cbase = c0 + scanhalf * 32;
#pragma unroll 8
            for (int cl = 0; cl < 32; cl++) {
                float v = cn[cl] - 2.0f * sD[cl];
                if (v < worst) {
                    float mx = cd[0]; int ms = 0;
#pragma unroll
                    for (int s = 1; s < KCAND; s++)
                        if (cd[s] > mx) { mx = cd[s]; ms = s; }
#pragma unroll
                    for (int s = 0; s < KCAND; s++)
                        if (s == ms) { cd[s] = v; ci[s] = cbase + cl; }
                    float w = cd[0];
#pragma unroll
                    for (int s = 1; s < KCAND; s++) w = fmaxf(w, cd[s]);
                    worst = w;
                }
            }
        }
        __syncthreads();   // sD dead before next chunk's B staging
    }

    // dump candidates: 16 per row
#pragma unroll
    for (int s = 0; s < KCAND; s++)
        cands[scanrow * 16 + scanhalf * KCAND + s] = ci[s];
    __syncthreads();

    // ==== two 64-row half-passes: exact fp32 rescore + epilogue ====
    double lsum = 0.0;
    for (int hp = 0; hp < 2; hp++) {
        size_t xb2 = xbase + hp * 64;

        // ---- stage x fp32 tile [64 rows][e], stride XS_STRIDE ----
#pragma unroll
        for (int i = 0; i < 16; i++) {             // 4096 float4 tasks
            int f4 = tid + i * NTHREADS;
            int e  = f4 >> 4;
            int t4 = (f4 & 15) << 2;
            float4 v = *(const float4*)(src + xb2 + (size_t)e * Tt + t4);
            xs[(t4 + 0) * XS_STRIDE + e] = v.x;
            xs[(t4 + 1) * XS_STRIDE + e] = v.y;
            xs[(t4 + 2) * XS_STRIDE + e] = v.z;
            xs[(t4 + 3) * XS_STRIDE + e] = v.w;
        }
        __syncthreads();

        // ---- xnorm: canonical sequential order (matches round-1 exactly) ----
        if (tid < 64) {
            float s = 0.f;
            const float* xr = xs + tid * XS_STRIDE;
            for (int e = 0; e < Ee; e++) s = __fadd_rn(s, __fmul_rn(xr[e], xr[e]));
            sxn[tid] = s;
        }
        __syncthreads();

        // ---- exact fp32 rescore: 4 threads per row, 4 cands each ----
        {
            int row = tid >> 2;                     // 0..63 (local)
            int grow = hp * 64 + row;               // 0..127
            int cbase = (tid & 3) * 4;
            const float* xr = xs + row * XS_STRIDE;
            float xn = sxn[row];
            unsigned long long best = ~0ull;
#pragma unroll
            for (int cj = 0; cj < 4; cj++) {
                int c = cands[grow * 16 + cbase + cj];
                const float* cw = cbg + (size_t)c * Ee;
                float acc = 0.f;
#pragma unroll 4
                for (int k = 0; k < Ee; k++) acc = fmaf(xr[k], __ldg(cw + k), acc);
                float d = __fsub_rn(__fadd_rn(xn, cnorm[g * NCc + c]), 2.0f * acc);
                unsigned long long key =
                    ((unsigned long long)__float_as_uint(d) << 32) | (unsigned)c;
                best = (key < best) ? key : best;
            }
            unsigned long long o = __shfl_xor_sync(0xffffffffu, best, 1);
            best = (o < best) ? o : best;
            o = __shfl_xor_sync(0xffffffffu, best, 2);
            best = (o < best) ? o : best;
            if ((tid & 3) == 0) win[row] = (int)(best & 0xffffffffu);
        }
        __syncthreads();

        if (tid < 64) idxout[g * Nrows + n0 + hp * 64 + tid] = (float)win[tid];

        // ---- epilogue: q / resid / loss for these 64 rows ----
#pragma unroll 4
        for (int it = 0; it < (Ee * 64) / NTHREADS; it++) {    // 64
            int elem = it * NTHREADS + tid;
            int e = elem >> 6;
            int m = elem & 63;
            int c = win[m];
            float zq = __ldg(cbg + (size_t)c * Ee + e);
            float x  = xs[m * XS_STRIDE + e];
            float diff = __fsub_rn(zq, x);
            float st   = __fadd_rn(x, diff);
            size_t off = xb2 + (size_t)e * Tt + m;
            if (step) {
                qout[off] = __fadd_rn(qout[off], st);
            } else {
                qout[off]    = st;
                g_resid[off] = __fsub_rn(x, st);
            }
            lsum += (double)diff * (double)diff;
        }
        __syncthreads();   // xs/win dead before next half-pass
    }

    // ---- deterministic block loss reduction ----
    sred[tid] = lsum;
    __syncthreads();
    for (int s2 = NTHREADS / 2; s2 > 0; s2 >>= 1) {
        if (tid < s2) sred[tid] = sred[tid] + sred[tid + s2];
        __syncthreads();
    }
    if (tid == 0) partial[g * ROWTILES + blockIdx.x] = sred[0];
}

// ---------------------------------------------------------------------------
__global__ void loss_kernel(float* __restrict__ out) {
    __shared__ double s0a[256], s1a[256];
    int tid = threadIdx.x;
    double a0 = g_partial[tid * 2] + g_partial[tid * 2 + 1];
    double a1 = g_partial[Gg * ROWTILES + tid * 2] +
                g_partial[Gg * ROWTILES + tid * 2 + 1];
    s0a[tid] = a0; s1a[tid] = a1;
    __syncthreads();
    for (int s = 128; s > 0; s >>= 1) {
        if (tid < s) { s0a[tid] += s0a[tid + s]; s1a[tid] += s1a[tid + s]; }
        __syncthreads();
    }
    if (tid == 0) {
        double l0 = 1.25 * (s0a[0] / (double)QELEMS);
        double l1 = 1.25 * (s1a[0] / (double)QELEMS);
        out[0] = (float)((l0 + l1) * 0.5);
    }
}

// ---------------------------------------------------------------------------
extern "C" void kernel_launch(void* const* d_in, const int* in_sizes, int n_in,
                              void* d_out, int out_size) {
    const float* xin = (const float*)d_in[0];
    const float* cb1 = (const float*)d_in[1];
    const float* cb2 = (const float*)d_in[2];
    float* out = (float*)d_out;

    float* qout    = out;
    float* lossout = out + QELEMS;
    float* idxout  = out + QELEMS + 1;

    cudaFuncSetAttribute(vq_step_mma,
                         cudaFuncAttributeMaxDynamicSharedMemorySize, SM_TOTAL);

    cnorm_kernel<<<(2 * Gg * NCc) / 8, 256>>>(cb1, cb2);

    dim3 grid(ROWTILES, Gg);
    vq_step_mma<<<grid, NTHREADS, SM_TOTAL>>>(xin, cb1, qout, idxout, 0);
    vq_step_mma<<<grid, NTHREADS, SM_TOTAL>>>(xin, cb2, qout,
                                              idxout + Gg * Nrows, 1);
    loss_kernel<<<1, 256>>>(lossout);
}

// round 10
// speedup vs baseline: 1.9383x; 1.9383x over previous
#include <cuda_runtime.h>
#include <cuda_bf16.h>
#include <cstdint>

// ---------------- problem constants ----------------
#define Bb 8
#define Cc 512
#define Tt 4096
#define Gg 2
#define NCc 1024
#define Ee 256
#define Nrows (Bb * Tt)          // 32768 rows per group
#define QELEMS (Bb * Cc * Tt)    // 16777216
#define BM 64                    // rows per CTA
#define BNC 64                   // codes per chunk
#define NCHUNK (NCc / BNC)       // 16
#define NTHREADS 256
#define ROWTILES (Nrows / BM)    // 512
#define KCAND 8

#define SAP 264                  // bf16 elems per staged row (528B, conflict-free ldmatrix)
#define SDP 68                   // float stride of D scratch tile

// ---------------- smem layout (bytes) ----------------
#define SM_A    0                             // 64*SAP bf16 = 33792
#define SM_B    (BM * SAP * 2)                // 33792: B stage / D overlay
#define SM_CN   (SM_B + BM * SAP * 2)         // 67584: 64 f32 cnorm chunk
#define SM_CAND (SM_CN + 256)                 // 67840: 64*8 ints = 2048
#define SM_XN   (SM_CAND + 2048)              // 69888: 64 f32
#define SM_WIN  (SM_XN + 256)                 // 70144: 64 ints
#define SM_RED  (SM_WIN + 256)                // 70400: 256 f64 = 2048
#define SM_TOTAL (SM_RED + 2048)              // 72448
#define XS_STRIDE 257                         // fp32 overlay at SM_A (65792 B)

// ---------------- scratch ----------------
__device__ float  g_resid[QELEMS];
__device__ float  g_cnorm[2 * Gg * NCc];
__device__ double g_partial[2 * Gg * ROWTILES];   // 2048

// ---------------- helpers ----------------
__device__ __forceinline__ uint32_t smem_u32(const void* p) {
    uint32_t a;
    asm("{ .reg .u64 t; cvta.to.shared.u64 t, %1; cvt.u32.u64 %0, t; }"
        : "=r"(a) : "l"(p));
    return a;
}

__device__ __forceinline__ void ldsm_x4(uint32_t* r, uint32_t addr) {
    asm volatile("ldmatrix.sync.aligned.m8n8.x4.shared.b16 {%0,%1,%2,%3}, [%4];"
                 : "=r"(r[0]), "=r"(r[1]), "=r"(r[2]), "=r"(r[3]) : "r"(addr));
}

__device__ __forceinline__ void mma16816(float* c, const uint32_t* a,
                                         uint32_t b0, uint32_t b1) {
    asm volatile(
        "mma.sync.aligned.m16n8k16.row.col.f32.bf16.bf16.f32 "
        "{%0,%1,%2,%3}, {%4,%5,%6,%7}, {%8,%9}, {%0,%1,%2,%3};"
        : "+f"(c[0]), "+f"(c[1]), "+f"(c[2]), "+f"(c[3])
        : "r"(a[0]), "r"(a[1]), "r"(a[2]), "r"(a[3]), "r"(b0), "r"(b1));
}

// ---------------------------------------------------------------------------
__global__ void cnorm_kernel(const float* __restrict__ cb1,
                             const float* __restrict__ cb2) {
    int gwarp = (blockIdx.x * blockDim.x + threadIdx.x) >> 5;
    int lane  = threadIdx.x & 31;
    if (gwarp >= 2 * Gg * NCc) return;
    const float* cb = (gwarp < Gg * NCc) ? cb1 : cb2;
    int row = gwarp & (Gg * NCc - 1);
    const float* p = cb + (size_t)row * Ee;
    float s = 0.f;
#pragma unroll
    for (int i = 0; i < Ee / 32; i++) {
        float v = p[lane + i * 32];
        s = __fadd_rn(s, __fmul_rn(v, v));
    }
#pragma unroll
    for (int off = 16; off; off >>= 1) s += __shfl_xor_sync(0xffffffffu, s, off);
    if (lane == 0) g_cnorm[gwarp] = s;
}

// ---------------------------------------------------------------------------
__global__ __launch_bounds__(NTHREADS, 2)
void vq_step_mma(const float* __restrict__ xin,
                 const float* __restrict__ cb,
                 float* __restrict__ qout,
                 float* __restrict__ idxout,
                 int step) {
    extern __shared__ char sm[];
    uint32_t smb = smem_u32(sm);
    float* cnormS = (float*)(sm + SM_CN);
    int*   cands  = (int*)(sm + SM_CAND);
    float* sxn    = (float*)(sm + SM_XN);
    int*   win    = (int*)(sm + SM_WIN);
    double* sred  = (double*)(sm + SM_RED);
    float* xs     = (float*)(sm + SM_A);          // fp32 overlay (x, then winners)

    const float* src = step ? g_resid : xin;
    const float* cnorm = g_cnorm + step * (Gg * NCc);
    double* partial = g_partial + step * (Gg * ROWTILES);

    int tid  = threadIdx.x;
    int lane = tid & 31;
    int wid  = tid >> 5;
    int wm   = wid & 3;         // m quarter (16 rows)
    int wn   = wid >> 2;        // n half (32 codes)
    int g    = blockIdx.y;
    int n0   = blockIdx.x * BM;
    int b    = n0 >> 12;
    int t0   = n0 & (Tt - 1);
    size_t xbase = ((size_t)b * Cc + (size_t)g * Ee) * Tt + t0;
    const float* cbg = cb + (size_t)g * NCc * Ee;

    // ---- stage A: x[64 t-rows x 256 e] fp32 -> bf16, row stride SAP ----
#pragma unroll
    for (int i = 0; i < 8; i++) {
        int f  = tid + i * NTHREADS;
        int e  = (f >> 4) << 1;
        int t4 = (f & 15) << 2;
        float4 v0 = *(const float4*)(src + xbase + (size_t)e * Tt + t4);
        float4 v1 = *(const float4*)(src + xbase + (size_t)(e + 1) * Tt + t4);
        __nv_bfloat162 h0 = __floats2bfloat162_rn(v0.x, v1.x);
        __nv_bfloat162 h1 = __floats2bfloat162_rn(v0.y, v1.y);
        __nv_bfloat162 h2 = __floats2bfloat162_rn(v0.z, v1.z);
        __nv_bfloat162 h3 = __floats2bfloat162_rn(v0.w, v1.w);
        *(uint32_t*)(sm + SM_A + (size_t)((t4 + 0) * SAP + e) * 2) = *(uint32_t*)&h0;
        *(uint32_t*)(sm + SM_A + (size_t)((t4 + 1) * SAP + e) * 2) = *(uint32_t*)&h1;
        *(uint32_t*)(sm + SM_A + (size_t)((t4 + 2) * SAP + e) * 2) = *(uint32_t*)&h2;
        *(uint32_t*)(sm + SM_A + (size_t)((t4 + 3) * SAP + e) * 2) = *(uint32_t*)&h3;
    }

    uint32_t aAddr = smb + SM_A +
        (uint32_t)(((wm * 16 + (lane & 15)) * SAP + ((lane >> 4) << 3)) * 2);
    uint32_t bAddr = smb + SM_B +
        (uint32_t)(((wn * 32 + (lane & 7) + ((lane >> 4) << 3)) * SAP +
                    (((lane >> 3) & 1) << 3)) * 2);

    float cd[KCAND];
    int   ci[KCAND];
#pragma unroll
    for (int s = 0; s < KCAND; s++) { cd[s] = __int_as_float(0x7f800000); ci[s] = 0; }
    float worst = __int_as_float(0x7f800000);

    for (int ct = 0; ct < NCHUNK; ct++) {
        int c0 = ct * BNC;
#pragma unroll
        for (int i = 0; i < 16; i++) {
            int f4 = tid + i * NTHREADS;
            int code = f4 >> 6;
            int k4 = (f4 & 63) << 2;
            float4 v = *(const float4*)(cbg + (size_t)(c0 + code) * Ee + k4);
            __nv_bfloat162 h0 = __floats2bfloat162_rn(v.x, v.y);
            __nv_bfloat162 h1 = __floats2bfloat162_rn(v.z, v.w);
            *(uint2*)(sm + SM_B + (size_t)(code * SAP + k4) * 2) =
                make_uint2(*(uint32_t*)&h0, *(uint32_t*)&h1);
        }
        if (tid < BNC) cnormS[tid] = cnorm[g * NCc + c0 + tid];
        __syncthreads();

        float acc[4][4];
#pragma unroll
        for (int j = 0; j < 4; j++)
#pragma unroll
            for (int r = 0; r < 4; r++) acc[j][r] = 0.f;

#pragma unroll 4
        for (int ks = 0; ks < 16; ks++) {
            uint32_t afr[4];
            ldsm_x4(afr, aAddr + (uint32_t)((ks * 16) * 2));
            uint32_t bfr[2][4];
#pragma unroll
            for (int jp = 0; jp < 2; jp++)
                ldsm_x4(bfr[jp], bAddr + (uint32_t)((jp * 16 * SAP + ks * 16) * 2));
#pragma unroll
            for (int j = 0; j < 4; j++)
                mma16816(acc[j], afr,
                         bfr[j >> 1][(j & 1) * 2], bfr[j >> 1][(j & 1) * 2 + 1]);
        }
        __syncthreads();

#pragma unroll
        for (int j = 0; j < 4; j++) {
            int m = wm * 16 + (lane >> 2);
            int n = wn * 32 + j * 8 + ((lane & 3) << 1);
            *(float2*)(sm + SM_B + (size_t)(m * SDP + n) * 4) =
                make_float2(acc[j][0], acc[j][1]);
            *(float2*)(sm + SM_B + (size_t)((m + 8) * SDP + n) * 4) =
                make_float2(acc[j][2], acc[j][3]);
        }
        __syncthreads();

        if (tid < BM) {
            const float* sD = (const float*)(sm + SM_B) + tid * SDP;
#pragma unroll 8
            for (int cl = 0; cl < BNC; cl++) {
                float v = cnormS[cl] - 2.0f * sD[cl];
                if (v < worst) {
                    float mx = cd[0]; int ms = 0;
#pragma unroll
                    for (int s = 1; s < KCAND; s++)
                        if (cd[s] > mx) { mx = cd[s]; ms = s; }
#pragma unroll
                    for (int s = 0; s < KCAND; s++)
                        if (s == ms) { cd[s] = v; ci[s] = c0 + cl; }
                    float w = cd[0];
#pragma unroll
                    for (int s = 1; s < KCAND; s++) w = fmaxf(w, cd[s]);
                    worst = w;
                }
            }
        }
        __syncthreads();
    }

    if (tid < BM) {
#pragma unroll
        for (int s = 0; s < KCAND; s++) cands[tid * KCAND + s] = ci[s];
    }
    __syncthreads();

    // ---- overlay: stage x fp32 tile [row][e] stride XS_STRIDE ----
#pragma unroll
    for (int i = 0; i < 16; i++) {
        int f4 = tid + i * NTHREADS;
        int e  = f4 >> 4;
        int t4 = (f4 & 15) << 2;
        float4 v = *(const float4*)(src + xbase + (size_t)e * Tt + t4);
        xs[(t4 + 0) * XS_STRIDE + e] = v.x;
        xs[(t4 + 1) * XS_STRIDE + e] = v.y;
        xs[(t4 + 2) * XS_STRIDE + e] = v.z;
        xs[(t4 + 3) * XS_STRIDE + e] = v.w;
    }
    __syncthreads();

    // ---- xnorm: canonical sequential order (bit-identical to round 1/7) ----
    if (tid < BM) {
        float s = 0.f;
        const float* xr = xs + tid * XS_STRIDE;
        for (int e = 0; e < Ee; e++) s = __fadd_rn(s, __fmul_rn(xr[e], xr[e]));
        sxn[tid] = s;
    }
    __syncthreads();

    // ---- warp-cooperative rescore; margin-guarded exact fallback ----
    // MARGIN must exceed 2x the max deviation between the butterfly dot and
    // the canonical sequential chain. d ~ 256 => ulp ~3.05e-5; deviation
    // <= 1 ulp per candidate. 2e-4 (~6-13 ulp) is a safe guard band; any
    // potential order flip or tie lands in the exact fallback below.
    {
        const float INF = __int_as_float(0x7f800000);
        const float MARGIN = 2e-4f;
        for (int i = 0; i < 8; i++) {
            int row = wid * 8 + i;
            float xn = sxn[row];
            const float* xr = xs + row * XS_STRIDE;
            float vals[KCAND];
            int   cs[KCAND];
#pragma unroll
            for (int j = 0; j < KCAND; j++) {
                int c = cands[row * KCAND + j];
                cs[j] = c;
                const float* cw = cbg + (size_t)c * Ee;
                float p = 0.f;
#pragma unroll
                for (int q = 0; q < 8; q++)
                    p = fmaf(xr[lane + q * 32], __ldg(cw + lane + q * 32), p);
#pragma unroll
                for (int off = 16; off; off >>= 1)
                    p += __shfl_xor_sync(0xffffffffu, p, off);
                vals[j] = xn + cnorm[g * NCc + c] - 2.0f * p;
            }
            float b1 = vals[0], b2 = INF; int j1 = 0;
#pragma unroll
            for (int j = 1; j < KCAND; j++) {
                if (vals[j] < b1) { b2 = b1; b1 = vals[j]; j1 = j; }
                else if (vals[j] < b2) b2 = vals[j];
            }
            int winner;
            if (b2 - b1 < MARGIN) {
                // exact fallback: lanes 0-7 recompute all cands with the
                // bit-exact sequential chain (identical to round-7 rescore),
                // packed-key min with smaller-index tie-break.
                unsigned long long key = ~0ull;
                if (lane < KCAND) {
                    int c = cs[lane];
                    const float* cw = cbg + (size_t)c * Ee;
                    float acc2 = 0.f;
                    for (int k = 0; k < Ee; k++)
                        acc2 = fmaf(xr[k], __ldg(cw + k), acc2);
                    float d = __fsub_rn(__fadd_rn(xn, cnorm[g * NCc + c]),
                                        2.0f * acc2);
                    key = ((unsigned long long)__float_as_uint(d) << 32) |
                          (unsigned)c;
                }
#pragma unroll
                for (int off = 16; off; off >>= 1) {
                    unsigned long long o = __shfl_xor_sync(0xffffffffu, key, off);
                    key = (o < key) ? o : key;
                }
                winner = (int)(key & 0xffffffffu);
            } else {
                winner = cs[j1];
            }
            if (lane == 0) win[row] = winner;
        }
    }
    __syncthreads();

    if (tid < BM) idxout[g * Nrows + n0 + tid] = (float)win[tid];

    // ---- stage winner codewords into xs region (coalesced) ----
    __syncthreads();
#pragma unroll
    for (int i = 0; i < 16; i++) {
        int f4 = tid + i * NTHREADS;
        int m  = f4 >> 6;                 // winner row 0..63
        int k4 = (f4 & 63) << 2;
        int c = win[m];
        float4 v = *(const float4*)(cbg + (size_t)c * Ee + k4);
        float* dst = xs + m * XS_STRIDE + k4;
        dst[0] = v.x; dst[1] = v.y; dst[2] = v.z; dst[3] = v.w;
    }
    __syncthreads();

    // ---- epilogue: q / resid / loss (x re-read from gmem, zq from smem) ----
    double lsum = 0.0;
#pragma unroll 4
    for (int it = 0; it < (Ee * BM) / NTHREADS; it++) {    // 64
        int elem = it * NTHREADS + tid;
        int e = elem >> 6;
        int m = elem & 63;
        float zq = xs[m * XS_STRIDE + e];
        size_t off = xbase + (size_t)e * Tt + m;
        float x  = src[off];
        float diff = __fsub_rn(zq, x);
        float st   = __fadd_rn(x, diff);
        if (step) {
            qout[off] = __fadd_rn(qout[off], st);
        } else {
            qout[off]    = st;
            g_resid[off] = __fsub_rn(x, st);
        }
        lsum += (double)diff * (double)diff;
    }

    __syncthreads();
    sred[tid] = lsum;
    __syncthreads();
    for (int s2 = NTHREADS / 2; s2 > 0; s2 >>= 1) {
        if (tid < s2) sred[tid] = sred[tid] + sred[tid + s2];
        __syncthreads();
    }
    if (tid == 0) partial[g * ROWTILES + blockIdx.x] = sred[0];
}

// ---------------------------------------------------------------------------
__global__ void loss_kernel(float* __restrict__ out) {
    __shared__ double s0a[256], s1a[256];
    int tid = threadIdx.x;
    double a0 = 0.0, a1 = 0.0;
#pragma unroll
    for (int i = 0; i < 4; i++) {
        a0 += g_partial[tid * 4 + i];
        a1 += g_partial[Gg * ROWTILES + tid * 4 + i];
    }
    s0a[tid] = a0; s1a[tid] = a1;
    __syncthreads();
    for (int s = 128; s > 0; s >>= 1) {
        if (tid < s) { s0a[tid] += s0a[tid + s]; s1a[tid] += s1a[tid + s]; }
        __syncthreads();
    }
    if (tid == 0) {
        double l0 = 1.25 * (s0a[0] / (double)QELEMS);
        double l1 = 1.25 * (s1a[0] / (double)QELEMS);
        out[0] = (float)((l0 + l1) * 0.5);
    }
}

// ---------------------------------------------------------------------------
extern "C" void kernel_launch(void* const* d_in, const int* in_sizes, int n_in,
                              void* d_out, int out_size) {
    const float* xin = (const float*)d_in[0];
    const float* cb1 = (const float*)d_in[1];
    const float* cb2 = (const float*)d_in[2];
    float* out = (float*)d_out;

    float* qout    = out;
    float* lossout = out + QELEMS;
    float* idxout  = out + QELEMS + 1;

    cudaFuncSetAttribute(vq_step_mma,
                         cudaFuncAttributeMaxDynamicSharedMemorySize, SM_TOTAL);

    cnorm_kernel<<<(2 * Gg * NCc) / 8, 256>>>(cb1, cb2);

    dim3 grid(ROWTILES, Gg);
    vq_step_mma<<<grid, NTHREADS, SM_TOTAL>>>(xin, cb1, qout, idxout, 0);
    vq_step_mma<<<grid, NTHREADS, SM_TOTAL>>>(xin, cb2, qout,
                                              idxout + Gg * Nrows, 1);
    loss_kernel<<<1, 256>>>(lossout);
}